// round 7
// baseline (speedup 1.0000x reference)
#include <cuda_runtime.h>
#include <cuda_bf16.h>
#include <math.h>
#include <stdint.h>

// Problem constants
#define Bn  32
#define Cc  80
#define TXn 512
#define TYn 2048
#define K2  160          // stacked K: [scale(80); mean*scale(80)]
#define NEGV (-1e9f)
#define LOG2PI 1.8378770664093453f
#define CHY 512          // y-chunk for gemm/fwd pipelining
#define NCH (TYn/CHY)    // 4

// Output layout (flat f32, reference return order)
#define Z_OFF        0
#define YMEAN_OFF    (Bn*Cc*TYn)
#define YLOG_OFF     (2*Bn*Cc*TYn)
#define ATTN_OFF     (3*Bn*Cc*TYn)
#define ODUR_OFF     (ATTN_OFF + Bn*TYn*TXn)
#define OADUR_OFF    (ODUR_OFF + Bn*TXn)

// -------------------- scratch (__device__ globals) --------------------------
__device__ float    g_W[Bn*K2*TXn];              // [b][k][x]
__device__ float    g_Z[Bn*K2*TYn];              // [b][k][y]
__device__ float    g_rowA[Bn*TXn];              // logp1+logp4 per (b,x)
__device__ float    g_logpT[(size_t)Bn*TYn*TXn]; // 134 MB [b][y][x]
__device__ unsigned g_dbits[(size_t)Bn*TYn*16];  // dir bits, 32 per warp-word
__device__ float    g_vst[Bn*TXn];               // fwd DP state between chunks
__device__ int      g_xy[Bn*TYn];                // alignment index per (b,y)
__device__ int      g_cnt[Bn*TXn];               // per-x duration counts

// -------------------- K1: per-(b,x) prep -------------------------------------
__global__ void prepx_kernel(const float* __restrict__ om,
                             const float* __restrict__ ols,
                             const float* __restrict__ odur,
                             float* __restrict__ out)
{
    int i = blockIdx.x * blockDim.x + threadIdx.x;
    if (i >= Bn*TXn) return;
    int b = i / TXn, x = i % TXn;
    const float* omb = om  + (size_t)b*Cc*TXn + x;
    const float* olb = ols + (size_t)b*Cc*TXn + x;
    float* wS = g_W + (size_t)b*K2*TXn + x;
    float sa = 0.f;
    #pragma unroll 4
    for (int c = 0; c < Cc; c++) {
        float l  = olb[(size_t)c*TXn];
        float sc = expf(-2.f*l);
        float m  = omb[(size_t)c*TXn];
        wS[(size_t)c*TXn]        = sc;
        wS[(size_t)(Cc+c)*TXn]   = m*sc;
        sa += -0.5f*LOG2PI - l - 0.5f*m*m*sc;
    }
    g_rowA[i] = sa;
    g_cnt[i]  = 0;
    out[ODUR_OFF + i] = odur[i];
}

// -------------------- K2: z masking + Z matrix --------------------------------
__global__ void prepz_kernel(const float* __restrict__ z,
                             const int* __restrict__ yl,
                             float* __restrict__ out)
{
    int i = blockIdx.x * blockDim.x + threadIdx.x;
    if (i >= Bn*Cc*TYn) return;
    int b = i / (Cc*TYn);
    int r = i % (Cc*TYn);
    int c = r / TYn;
    int y = r % TYn;
    float zv = z[i];
    if (y >= yl[b]) zv = 0.f;
    out[Z_OFF + i] = zv;
    size_t zb = (size_t)b*K2*TYn;
    g_Z[zb + (size_t)c*TYn + y]      = -0.5f*zv*zv;
    g_Z[zb + (size_t)(Cc+c)*TYn + y] = zv;
}

// -------------------- K3: logp GEMM (128x128 tile, band-pruned) ---------------
__global__ void __launch_bounds__(256, 2)
gemm_kernel(const int* __restrict__ xl, const int* __restrict__ yl, int ybase)
{
    int b  = blockIdx.z;
    int x0 = blockIdx.x * 128;
    int y0 = ybase + blockIdx.y * 128;
    int xlen = xl[b], ylen = yl[b];
    if (x0 >= xlen || y0 >= ylen) return;
    // band pruning: tiles never consumed by the Viterbi DP / backtrack
    if (x0 > y0 + 127) return;                      // entirely above diagonal (x>j)
    if (x0 + 127 < y0 - (ylen - xlen)) return;      // entirely below reachable band

    __shared__ float zs[16][128];   // k x y
    __shared__ float ws[16][128];   // k x x

    int tid  = threadIdx.x;
    int lrow = tid >> 4;            // 0..15
    int lcol = (tid & 15) << 3;     // 0..120
    int ty   = tid >> 4;            // 0..15
    int tx   = tid & 15;            // 0..15

    const float* Zb = g_Z + (size_t)b*K2*TYn;
    const float* Wb = g_W + (size_t)b*K2*TXn;

    float acc[8][8] = {};

    for (int k0 = 0; k0 < K2; k0 += 16) {
        const float* zp = Zb + (size_t)(k0+lrow)*TYn + y0 + lcol;
        const float* wp = Wb + (size_t)(k0+lrow)*TXn + x0 + lcol;
        *(float4*)&zs[lrow][lcol]   = *(const float4*)zp;
        *(float4*)&zs[lrow][lcol+4] = *(const float4*)(zp+4);
        *(float4*)&ws[lrow][lcol]   = *(const float4*)wp;
        *(float4*)&ws[lrow][lcol+4] = *(const float4*)(wp+4);
        __syncthreads();
        #pragma unroll
        for (int k = 0; k < 16; k++) {
            float4 z0 = *(float4*)&zs[k][ty<<3];
            float4 z1 = *(float4*)&zs[k][(ty<<3)+4];
            float4 w0 = *(float4*)&ws[k][tx<<3];
            float4 w1 = *(float4*)&ws[k][(tx<<3)+4];
            float za[8] = {z0.x,z0.y,z0.z,z0.w,z1.x,z1.y,z1.z,z1.w};
            float wa[8] = {w0.x,w0.y,w0.z,w0.w,w1.x,w1.y,w1.z,w1.w};
            #pragma unroll
            for (int i = 0; i < 8; i++)
                #pragma unroll
                for (int j = 0; j < 8; j++)
                    acc[i][j] += za[i]*wa[j];
        }
        __syncthreads();
    }

    float ra[8];
    #pragma unroll
    for (int j = 0; j < 8; j++)
        ra[j] = g_rowA[b*TXn + x0 + (tx<<3) + j];

    #pragma unroll
    for (int i = 0; i < 8; i++) {
        int y = y0 + (ty<<3) + i;
        float* op = g_logpT + ((size_t)b*TYn + y)*TXn + x0 + (tx<<3);
        float4 o0, o1;
        float* p0 = (float*)&o0; float* p1 = (float*)&o1;
        bool yok = (y < ylen);
        #pragma unroll
        for (int j = 0; j < 4; j++) {
            int xa = x0 + (tx<<3) + j;
            int xb = xa + 4;
            p0[j] = (yok && xa < xlen) ? (acc[i][j]   + ra[j])   : 0.f;
            p1[j] = (yok && xb < xlen) ? (acc[i][j+4] + ra[j+4]) : 0.f;
        }
        *(float4*)op       = o0;
        *(float4*)(op + 4) = o1;
    }
}

// -------------------- K4: forward Viterbi chunk (16 warps, skewed wavefront) ---
// 512 threads, 1 x per thread, warp w handles phase q = P - w (8 columns).
// Per-warp boundary slots sbuf[w][(j+1)&31]; parity prefetch buffers c0/c1
// reloaded in place for phase q+2 (no copies, ~2-phase load slack).
__global__ void __launch_bounds__(512)
fwd_kernel(const int* __restrict__ xl, const int* __restrict__ yl, int j0c)
{
    int b    = blockIdx.x;
    int x    = threadIdx.x;
    int w    = x >> 5, lane = x & 31;
    int xlen = xl[b], ylen = yl[b];
    int jend = min(ylen, j0c + CHY);
    if (j0c >= jend) return;

    __shared__ float sbuf[16][32];   // [warp][column mod 32]

    unsigned force;
    {
        int rel = xlen - (w << 5);
        if (rel <= 0)      force = 0xFFFFFFFFu;
        else if (rel < 32) force = 0xFFFFFFFFu << rel;
        else               force = 0u;
    }
    int mlim = (w << 5) + 31;        // x>j possible only when j < mlim

    float v = (j0c == 0) ? 0.f : g_vst[b*TXn + x];
    if (lane == 31) sbuf[w][0] = v;  // boundary entering column j0c (j0c%32==0)

    const float* base  = g_logpT + (size_t)b*TYn*TXn + x;
    unsigned*    dbase = g_dbits + (size_t)b*TYn*16 + w;

    int nph = (jend - j0c + 7) >> 3;

    float c0[8], c1[8];
    #pragma unroll
    for (int d = 0; d < 8; d++) {
        int ja = j0c + d, jb = j0c + 8 + d;
        c0[d] = (ja < jend) ? base[(size_t)ja*TXn] : 0.f;
        c1[d] = (jb < jend) ? base[(size_t)jb*TXn] : 0.f;
    }
    __syncthreads();

    auto colbody = [&](float (&CB)[8], int j0) {
        float rb[8];
        if (w > 0) {
            #pragma unroll
            for (int d = 0; d < 8; d++) rb[d] = sbuf[w-1][(j0 + d) & 31];
        }
        #pragma unroll
        for (int d = 0; d < 8; d++) {
            int j = j0 + d;
            if (j < jend) {
                float cv = CB[d];
                int jp = j + 16;                       // reload slot for q+2
                CB[d] = (jp < jend) ? base[(size_t)jp*TXn] : 0.f;

                float left = __shfl_up_sync(0xFFFFFFFFu, v, 1);
                if (lane == 0) left = (w == 0) ? NEGV : rb[d];

                bool  di = v >= left;
                float nv = fmaxf(v, left) + cv;
                if (j < mlim) { if (x > j) nv = NEGV; }

                unsigned bits = __ballot_sync(0xFFFFFFFFu, di) | force;
                if (lane == 0) dbase[(size_t)j*16] = bits;

                v = nv;
                if (lane == 31) sbuf[w][(j + 1) & 31] = v;
            }
        }
    };

    int NP = nph + 15;
    for (int P = 0; P < NP; P++) {
        int q = P - w;
        if (q >= 0 && q < nph) {
            int j0 = j0c + (q << 3);
            if ((q & 1) == 0) colbody(c0, j0);
            else              colbody(c1, j0);
        }
        __syncthreads();
    }

    g_vst[b*TXn + x] = v;
}

// -------------------- K5: backtrack + count (1 warp per batch, 32-bit words) ---
__global__ void __launch_bounds__(32)
bwd_kernel(const int* __restrict__ xl, const int* __restrict__ yl)
{
    int b = blockIdx.x, lane = threadIdx.x;
    int xlen = xl[b], ylen = yl[b];

    for (int j = ylen + lane; j < TYn; j += 32) g_xy[b*TYn + j] = 0;

    int idx = xlen - 1;
    for (int jhi = ylen - 1; jhi >= 0; jhi -= 32) {
        int steps = min(32, jhi + 1);
        int j = jhi - lane;
        int w0 = idx >> 5;                 // spans at most 2 words over 32 steps
        unsigned d0 = 0xFFFFFFFFu, d1 = 0xFFFFFFFFu;
        if (lane < steps) {
            const unsigned* p = g_dbits + ((size_t)b*TYn + j)*16;
            d0 = p[w0];
            if (w0 >= 1) d1 = p[w0-1];
        }
        int myidx = 0;
        for (int s = 0; s < steps; s++) {
            unsigned sel  = (w0 == (idx >> 5)) ? d0 : d1;
            unsigned word = __shfl_sync(0xFFFFFFFFu, sel, s);
            if (lane == s) myidx = idx;
            idx += (int)((word >> (idx & 31)) & 1u) - 1;
        }
        if (lane < steps) {
            g_xy[b*TYn + jhi - lane] = myidx;
            atomicAdd(&g_cnt[b*TXn + myidx], 1);
        }
    }
}

// -------------------- K6: y_mean / y_log_scale gathers -------------------------
__global__ void gather_kernel(const float* __restrict__ om,
                              const float* __restrict__ ols,
                              const int* __restrict__ yl,
                              float* __restrict__ out)
{
    int i = blockIdx.x * blockDim.x + threadIdx.x;
    if (i >= Bn*Cc*TYn) return;
    int b = i / (Cc*TYn);
    int r = i % (Cc*TYn);
    int c = r / TYn;
    int y = r % TYn;
    float m = 0.f, s = 0.f;
    if (y < yl[b]) {
        int x = g_xy[b*TYn + y];
        m = om [(size_t)(b*Cc + c)*TXn + x];
        s = ols[(size_t)(b*Cc + c)*TXn + x];
    }
    out[YMEAN_OFF + i] = m;
    out[YLOG_OFF  + i] = s;
}

// -------------------- K7: attn_out (zero + one-hot scatter) --------------------
__global__ void attn_kernel(const int* __restrict__ yl, float* __restrict__ out)
{
    int y = blockIdx.x, b = blockIdx.y, t = threadIdx.x;
    int xi = (y < yl[b]) ? g_xy[b*TYn + y] : -1;
    int x4 = t << 2;
    float4 r = make_float4(0.f, 0.f, 0.f, 0.f);
    if (xi >= x4 && xi < x4 + 4) ((float*)&r)[xi - x4] = 1.0f;
    *(float4*)&out[ATTN_OFF + ((size_t)b*TYn + y)*TXn + x4] = r;
}

// -------------------- K8: o_attn_dur --------------------------------------------
__global__ void dur_kernel(const int* __restrict__ xl, float* __restrict__ out)
{
    int i = blockIdx.x * blockDim.x + threadIdx.x;
    if (i >= Bn*TXn) return;
    int b = i / TXn, x = i % TXn;
    out[OADUR_OFF + i] = (x < xl[b]) ? log1pf((float)g_cnt[i]) : 0.f;
}

// -------------------- launch: gemm chunk k overlaps fwd chunk k-1 ---------------
extern "C" void kernel_launch(void* const* d_in, const int* in_sizes, int n_in,
                              void* d_out, int out_size)
{
    const float* om   = (const float*)d_in[0];
    const float* ols  = (const float*)d_in[1];
    const float* odur = (const float*)d_in[2];
    const float* z    = (const float*)d_in[3];
    const int*   xlen = (const int*)  d_in[4];
    const int*   ylen = (const int*)  d_in[5];
    float* out = (float*)d_out;

    static cudaStream_t s2;
    static cudaEvent_t evA, evG[NCH], evB, evT;
    static bool init_done = false;
    if (!init_done) {
        cudaStreamCreateWithFlags(&s2, cudaStreamNonBlocking);
        cudaEventCreateWithFlags(&evA, cudaEventDisableTiming);
        for (int k = 0; k < NCH; k++)
            cudaEventCreateWithFlags(&evG[k], cudaEventDisableTiming);
        cudaEventCreateWithFlags(&evB, cudaEventDisableTiming);
        cudaEventCreateWithFlags(&evT, cudaEventDisableTiming);
        init_done = true;
    }

    prepx_kernel<<<(Bn*TXn + 255)/256, 256>>>(om, ols, odur, out);
    prepz_kernel<<<(Bn*Cc*TYn + 255)/256, 256>>>(z, ylen, out);
    cudaEventRecord(evA, 0);

    cudaStreamWaitEvent(s2, evA, 0);
    for (int k = 0; k < NCH; k++) {
        gemm_kernel<<<dim3(TXn/128, CHY/128, Bn), 256, 0, s2>>>(xlen, ylen, k*CHY);
        cudaEventRecord(evG[k], s2);
    }

    for (int k = 0; k < NCH; k++) {
        cudaStreamWaitEvent(0, evG[k], 0);
        fwd_kernel<<<Bn, 512>>>(xlen, ylen, k*CHY);
    }

    bwd_kernel<<<Bn, 32>>>(xlen, ylen);
    cudaEventRecord(evB, 0);

    cudaStreamWaitEvent(s2, evB, 0);
    attn_kernel<<<dim3(TYn, Bn), 128, 0, s2>>>(ylen, out);
    cudaEventRecord(evT, s2);

    gather_kernel<<<(Bn*Cc*TYn + 255)/256, 256>>>(om, ols, ylen, out);
    dur_kernel<<<(Bn*TXn + 255)/256, 256>>>(xlen, out);
    cudaStreamWaitEvent(0, evT, 0);
}

// round 8
// speedup vs baseline: 1.1897x; 1.1897x over previous
#include <cuda_runtime.h>
#include <cuda_bf16.h>
#include <math.h>
#include <stdint.h>

// Problem constants
#define Bn  32
#define Cc  80
#define TXn 512
#define TYn 2048
#define K2  160          // stacked K: [scale(80); mean*scale(80)]
#define NEGV (-1e9f)
#define LOG2PI 1.8378770664093453f

// Output layout (flat f32, reference return order)
#define Z_OFF        0
#define YMEAN_OFF    (Bn*Cc*TYn)
#define YLOG_OFF     (2*Bn*Cc*TYn)
#define ATTN_OFF     (3*Bn*Cc*TYn)
#define ODUR_OFF     (ATTN_OFF + Bn*TYn*TXn)
#define OADUR_OFF    (ODUR_OFF + Bn*TXn)

// fwd smem: 16 warps x padded row of boundary values + 16 progress counters
#define SBW 2064
#define SMEM_FWD (16*SBW*4 + 64)

// -------------------- scratch (__device__ globals) --------------------------
__device__ float    g_W[Bn*K2*TXn];              // [b][k][x]
__device__ float    g_Z[Bn*K2*TYn];              // [b][k][y]
__device__ float    g_rowA[Bn*TXn];              // logp1+logp4 per (b,x)
__device__ float    g_logpT[(size_t)Bn*TYn*TXn]; // 134 MB [b][y][x]
__device__ unsigned g_dbits[(size_t)Bn*TYn*16];  // dir bits, 32 per warp-word
__device__ int      g_xy[Bn*TYn];                // alignment index per (b,y)
__device__ int      g_cnt[Bn*TXn];               // per-x duration counts

// -------------------- K1: per-(b,x) prep -------------------------------------
__global__ void prepx_kernel(const float* __restrict__ om,
                             const float* __restrict__ ols,
                             const float* __restrict__ odur,
                             float* __restrict__ out)
{
    int i = blockIdx.x * blockDim.x + threadIdx.x;
    if (i >= Bn*TXn) return;
    int b = i / TXn, x = i % TXn;
    const float* omb = om  + (size_t)b*Cc*TXn + x;
    const float* olb = ols + (size_t)b*Cc*TXn + x;
    float* wS = g_W + (size_t)b*K2*TXn + x;
    float sa = 0.f;
    #pragma unroll 4
    for (int c = 0; c < Cc; c++) {
        float l  = olb[(size_t)c*TXn];
        float sc = expf(-2.f*l);
        float m  = omb[(size_t)c*TXn];
        wS[(size_t)c*TXn]        = sc;
        wS[(size_t)(Cc+c)*TXn]   = m*sc;
        sa += -0.5f*LOG2PI - l - 0.5f*m*m*sc;
    }
    g_rowA[i] = sa;
    g_cnt[i]  = 0;
    out[ODUR_OFF + i] = odur[i];
}

// -------------------- K2: z masking + Z matrix --------------------------------
__global__ void prepz_kernel(const float* __restrict__ z,
                             const int* __restrict__ yl,
                             float* __restrict__ out)
{
    int i = blockIdx.x * blockDim.x + threadIdx.x;
    if (i >= Bn*Cc*TYn) return;
    int b = i / (Cc*TYn);
    int r = i % (Cc*TYn);
    int c = r / TYn;
    int y = r % TYn;
    float zv = z[i];
    if (y >= yl[b]) zv = 0.f;
    out[Z_OFF + i] = zv;
    size_t zb = (size_t)b*K2*TYn;
    g_Z[zb + (size_t)c*TYn + y]      = -0.5f*zv*zv;
    g_Z[zb + (size_t)(Cc+c)*TYn + y] = zv;
}

// -------------------- K3: logp GEMM (128x128 tile, band-pruned) ---------------
__global__ void __launch_bounds__(256, 2)
gemm_kernel(const int* __restrict__ xl, const int* __restrict__ yl)
{
    int b  = blockIdx.z;
    int x0 = blockIdx.x * 128;
    int y0 = blockIdx.y * 128;
    int xlen = xl[b], ylen = yl[b];
    if (x0 >= xlen || y0 >= ylen) return;
    // band pruning: tiles never consumed by the Viterbi DP / backtrack
    if (x0 > y0 + 127) return;                      // entirely above diagonal (x>j)
    if (x0 + 127 < y0 - (ylen - xlen)) return;      // entirely below reachable band

    __shared__ float zs[16][128];   // k x y
    __shared__ float ws[16][128];   // k x x

    int tid  = threadIdx.x;
    int lrow = tid >> 4;            // 0..15
    int lcol = (tid & 15) << 3;     // 0..120
    int ty   = tid >> 4;            // 0..15
    int tx   = tid & 15;            // 0..15

    const float* Zb = g_Z + (size_t)b*K2*TYn;
    const float* Wb = g_W + (size_t)b*K2*TXn;

    float acc[8][8] = {};

    for (int k0 = 0; k0 < K2; k0 += 16) {
        const float* zp = Zb + (size_t)(k0+lrow)*TYn + y0 + lcol;
        const float* wp = Wb + (size_t)(k0+lrow)*TXn + x0 + lcol;
        *(float4*)&zs[lrow][lcol]   = *(const float4*)zp;
        *(float4*)&zs[lrow][lcol+4] = *(const float4*)(zp+4);
        *(float4*)&ws[lrow][lcol]   = *(const float4*)wp;
        *(float4*)&ws[lrow][lcol+4] = *(const float4*)(wp+4);
        __syncthreads();
        #pragma unroll
        for (int k = 0; k < 16; k++) {
            float4 z0 = *(float4*)&zs[k][ty<<3];
            float4 z1 = *(float4*)&zs[k][(ty<<3)+4];
            float4 w0 = *(float4*)&ws[k][tx<<3];
            float4 w1 = *(float4*)&ws[k][(tx<<3)+4];
            float za[8] = {z0.x,z0.y,z0.z,z0.w,z1.x,z1.y,z1.z,z1.w};
            float wa[8] = {w0.x,w0.y,w0.z,w0.w,w1.x,w1.y,w1.z,w1.w};
            #pragma unroll
            for (int i = 0; i < 8; i++)
                #pragma unroll
                for (int j = 0; j < 8; j++)
                    acc[i][j] += za[i]*wa[j];
        }
        __syncthreads();
    }

    float ra[8];
    #pragma unroll
    for (int j = 0; j < 8; j++)
        ra[j] = g_rowA[b*TXn + x0 + (tx<<3) + j];

    #pragma unroll
    for (int i = 0; i < 8; i++) {
        int y = y0 + (ty<<3) + i;
        float* op = g_logpT + ((size_t)b*TYn + y)*TXn + x0 + (tx<<3);
        float4 o0, o1;
        float* p0 = (float*)&o0; float* p1 = (float*)&o1;
        bool yok = (y < ylen);
        #pragma unroll
        for (int j = 0; j < 4; j++) {
            int xa = x0 + (tx<<3) + j;
            int xb = xa + 4;
            p0[j] = (yok && xa < xlen) ? (acc[i][j]   + ra[j])   : 0.f;
            p1[j] = (yok && xb < xlen) ? (acc[i][j+4] + ra[j+4]) : 0.f;
        }
        *(float4*)op       = o0;
        *(float4*)(op + 4) = o1;
    }
}

// -------------------- K4: forward Viterbi (decoupled warp wavefront) -----------
// 512 threads, 1 x per thread. NO CTA barriers in the main loop: warp w waits
// only on warp w-1 via an acquire/release progress counter in smem. Boundary
// values go to a full-length per-warp smem row (no ring, no overwrite).
__global__ void __launch_bounds__(512)
fwd_kernel(const int* __restrict__ xl, const int* __restrict__ yl)
{
    extern __shared__ float smemd[];
    float* sbuf = smemd;                      // [16][SBW]; sbuf[w][j] = boundary entering col j
    int*   prog = (int*)(smemd + 16*SBW);     // [16] columns completed per warp

    int b    = blockIdx.x;
    int x    = threadIdx.x;
    int w    = x >> 5, lane = x & 31;
    int xlen = xl[b], ylen = yl[b];

    unsigned force;
    {
        int rel = xlen - (w << 5);
        if (rel <= 0)      force = 0xFFFFFFFFu;
        else if (rel < 32) force = 0xFFFFFFFFu << rel;
        else               force = 0u;
    }
    int mlim = (w << 5) + 31;        // x>j possible only when j < mlim

    float v = 0.f;
    if (lane == 31) sbuf[w*SBW + 0] = 0.f;    // boundary entering column 0
    if (x < 16) prog[x] = 0;

    const float* base  = g_logpT + (size_t)b*TYn*TXn + x;
    unsigned*    dbase = g_dbits + (size_t)b*TYn*16 + w;

    int nph = (ylen + 7) >> 3;

    // parity prefetch buffers, reloaded in place for phase q+2
    float c0[8], c1[8];
    #pragma unroll
    for (int d = 0; d < 8; d++) {
        c0[d] = (d < ylen)     ? base[(size_t)d*TXn]       : 0.f;
        c1[d] = (8 + d < ylen) ? base[(size_t)(8 + d)*TXn] : 0.f;
    }
    __syncthreads();   // only barrier: init visibility

    unsigned prev_addr = (unsigned)__cvta_generic_to_shared(&prog[(w > 0) ? (w - 1) : 0]);
    unsigned my_addr   = (unsigned)__cvta_generic_to_shared(&prog[w]);

    auto colbody = [&](float (&CB)[8], int j0) {
        float rb[8];
        if (w > 0) {
            #pragma unroll
            for (int d = 0; d < 8; d++) rb[d] = sbuf[(w-1)*SBW + j0 + d];
        }
        #pragma unroll
        for (int d = 0; d < 8; d++) {
            int j = j0 + d;
            if (j < ylen) {                        // warp-uniform
                float cv = CB[d];
                int jp = j + 16;                   // reload slot for phase q+2
                CB[d] = (jp < ylen) ? base[(size_t)jp*TXn] : 0.f;

                float left = __shfl_up_sync(0xFFFFFFFFu, v, 1);
                if (lane == 0) left = (w == 0) ? NEGV : rb[d];

                bool  di = v >= left;
                float nv = fmaxf(v, left) + cv;
                if (j < mlim) { if (x > j) nv = NEGV; }

                unsigned bits = __ballot_sync(0xFFFFFFFFu, di) | force;
                if (lane == 0) dbase[(size_t)j*16] = bits;

                v = nv;
                if (lane == 31) sbuf[w*SBW + j + 1] = v;
            }
        }
    };

    for (int q = 0; q < nph; q++) {
        int j0    = q << 3;
        int jend8 = min(j0 + 8, ylen);

        if (w > 0) {
            int p;
            do {
                asm volatile("ld.acquire.cta.shared.b32 %0, [%1];"
                             : "=r"(p) : "r"(prev_addr) : "memory");
            } while (p < jend8);
        }

        if ((q & 1) == 0) colbody(c0, j0);
        else              colbody(c1, j0);

        if (lane == 31) {
            asm volatile("st.release.cta.shared.b32 [%0], %1;"
                         :: "r"(my_addr), "r"(jend8) : "memory");
        }
    }
}

// -------------------- K5: backtrack + count (1 warp per batch, 32-bit words) ---
__global__ void __launch_bounds__(32)
bwd_kernel(const int* __restrict__ xl, const int* __restrict__ yl)
{
    int b = blockIdx.x, lane = threadIdx.x;
    int xlen = xl[b], ylen = yl[b];

    for (int j = ylen + lane; j < TYn; j += 32) g_xy[b*TYn + j] = 0;

    int idx = xlen - 1;
    for (int jhi = ylen - 1; jhi >= 0; jhi -= 32) {
        int steps = min(32, jhi + 1);
        int j = jhi - lane;
        int w0 = idx >> 5;                 // spans at most 2 words over 32 steps
        unsigned d0 = 0xFFFFFFFFu, d1 = 0xFFFFFFFFu;
        if (lane < steps) {
            const unsigned* p = g_dbits + ((size_t)b*TYn + j)*16;
            d0 = p[w0];
            if (w0 >= 1) d1 = p[w0-1];
        }
        int myidx = 0;
        for (int s = 0; s < steps; s++) {
            unsigned sel  = (w0 == (idx >> 5)) ? d0 : d1;
            unsigned word = __shfl_sync(0xFFFFFFFFu, sel, s);
            if (lane == s) myidx = idx;
            idx += (int)((word >> (idx & 31)) & 1u) - 1;
        }
        if (lane < steps) {
            g_xy[b*TYn + jhi - lane] = myidx;
            atomicAdd(&g_cnt[b*TXn + myidx], 1);
        }
    }
}

// -------------------- K6: y_mean / y_log_scale gathers -------------------------
__global__ void gather_kernel(const float* __restrict__ om,
                              const float* __restrict__ ols,
                              const int* __restrict__ yl,
                              float* __restrict__ out)
{
    int i = blockIdx.x * blockDim.x + threadIdx.x;
    if (i >= Bn*Cc*TYn) return;
    int b = i / (Cc*TYn);
    int r = i % (Cc*TYn);
    int c = r / TYn;
    int y = r % TYn;
    float m = 0.f, s = 0.f;
    if (y < yl[b]) {
        int x = g_xy[b*TYn + y];
        m = om [(size_t)(b*Cc + c)*TXn + x];
        s = ols[(size_t)(b*Cc + c)*TXn + x];
    }
    out[YMEAN_OFF + i] = m;
    out[YLOG_OFF  + i] = s;
}

// -------------------- K7: attn_out (zero + one-hot scatter) --------------------
__global__ void attn_kernel(const int* __restrict__ yl, float* __restrict__ out)
{
    int y = blockIdx.x, b = blockIdx.y, t = threadIdx.x;
    int xi = (y < yl[b]) ? g_xy[b*TYn + y] : -1;
    int x4 = t << 2;
    float4 r = make_float4(0.f, 0.f, 0.f, 0.f);
    if (xi >= x4 && xi < x4 + 4) ((float*)&r)[xi - x4] = 1.0f;
    *(float4*)&out[ATTN_OFF + ((size_t)b*TYn + y)*TXn + x4] = r;
}

// -------------------- K8: o_attn_dur --------------------------------------------
__global__ void dur_kernel(const int* __restrict__ xl, float* __restrict__ out)
{
    int i = blockIdx.x * blockDim.x + threadIdx.x;
    if (i >= Bn*TXn) return;
    int b = i / TXn, x = i % TXn;
    out[OADUR_OFF + i] = (x < xl[b]) ? log1pf((float)g_cnt[i]) : 0.f;
}

// -------------------- launch (single stream — forks measured harmful) -----------
extern "C" void kernel_launch(void* const* d_in, const int* in_sizes, int n_in,
                              void* d_out, int out_size)
{
    const float* om   = (const float*)d_in[0];
    const float* ols  = (const float*)d_in[1];
    const float* odur = (const float*)d_in[2];
    const float* z    = (const float*)d_in[3];
    const int*   xlen = (const int*)  d_in[4];
    const int*   ylen = (const int*)  d_in[5];
    float* out = (float*)d_out;

    static bool attr_done = false;
    if (!attr_done) {
        cudaFuncSetAttribute(fwd_kernel,
                             cudaFuncAttributeMaxDynamicSharedMemorySize, SMEM_FWD);
        attr_done = true;
    }

    prepx_kernel<<<(Bn*TXn + 255)/256, 256>>>(om, ols, odur, out);
    prepz_kernel<<<(Bn*Cc*TYn + 255)/256, 256>>>(z, ylen, out);
    gemm_kernel<<<dim3(TXn/128, TYn/128, Bn), 256>>>(xlen, ylen);
    fwd_kernel<<<Bn, 512, SMEM_FWD>>>(xlen, ylen);
    bwd_kernel<<<Bn, 32>>>(xlen, ylen);
    gather_kernel<<<(Bn*Cc*TYn + 255)/256, 256>>>(om, ols, ylen, out);
    attn_kernel<<<dim3(TYn, Bn), 128>>>(ylen, out);
    dur_kernel<<<(Bn*TXn + 255)/256, 256>>>(xlen, out);
}

// round 9
// speedup vs baseline: 1.1994x; 1.0082x over previous
#include <cuda_runtime.h>
#include <cuda_bf16.h>
#include <math.h>
#include <stdint.h>

// Problem constants
#define Bn  32
#define Cc  80
#define TXn 512
#define TYn 2048
#define K2  160          // stacked K: [scale(80); mean*scale(80)]
#define NEGV (-1e9f)
#define LOG2PI 1.8378770664093453f

// Output layout (flat f32, reference return order)
#define Z_OFF        0
#define YMEAN_OFF    (Bn*Cc*TYn)
#define YLOG_OFF     (2*Bn*Cc*TYn)
#define ATTN_OFF     (3*Bn*Cc*TYn)
#define ODUR_OFF     (ATTN_OFF + Bn*TYn*TXn)
#define OADUR_OFF    (ODUR_OFF + Bn*TXn)

// -------------------- scratch (__device__ globals) --------------------------
__device__ float    g_W[Bn*K2*TXn];              // [b][k][x]
__device__ float    g_Z[Bn*K2*TYn];              // [b][k][y]
__device__ float    g_rowA[Bn*TXn];              // logp1+logp4 per (b,x)
__device__ float    g_logpT[(size_t)Bn*TYn*TXn]; // 134 MB [b][y][x]
__device__ unsigned g_dbits[(size_t)Bn*TYn*16];  // dir bits, 32 per warp-word
__device__ int      g_xy[Bn*TYn];                // alignment index per (b,y)
__device__ int      g_cnt[Bn*TXn];               // per-x duration counts

// -------------------- K1: per-(b,x) prep -------------------------------------
__global__ void prepx_kernel(const float* __restrict__ om,
                             const float* __restrict__ ols,
                             const float* __restrict__ odur,
                             float* __restrict__ out)
{
    int i = blockIdx.x * blockDim.x + threadIdx.x;
    if (i >= Bn*TXn) return;
    int b = i / TXn, x = i % TXn;
    const float* omb = om  + (size_t)b*Cc*TXn + x;
    const float* olb = ols + (size_t)b*Cc*TXn + x;
    float* wS = g_W + (size_t)b*K2*TXn + x;
    float sa = 0.f;
    #pragma unroll 4
    for (int c = 0; c < Cc; c++) {
        float l  = olb[(size_t)c*TXn];
        float sc = expf(-2.f*l);
        float m  = omb[(size_t)c*TXn];
        wS[(size_t)c*TXn]        = sc;
        wS[(size_t)(Cc+c)*TXn]   = m*sc;
        sa += -0.5f*LOG2PI - l - 0.5f*m*m*sc;
    }
    g_rowA[i] = sa;
    g_cnt[i]  = 0;
    out[ODUR_OFF + i] = odur[i];
}

// -------------------- K2: z masking + Z matrix --------------------------------
__global__ void prepz_kernel(const float* __restrict__ z,
                             const int* __restrict__ yl,
                             float* __restrict__ out)
{
    int i = blockIdx.x * blockDim.x + threadIdx.x;
    if (i >= Bn*Cc*TYn) return;
    int b = i / (Cc*TYn);
    int r = i % (Cc*TYn);
    int c = r / TYn;
    int y = r % TYn;
    float zv = z[i];
    if (y >= yl[b]) zv = 0.f;
    out[Z_OFF + i] = zv;
    size_t zb = (size_t)b*K2*TYn;
    g_Z[zb + (size_t)c*TYn + y]      = -0.5f*zv*zv;
    g_Z[zb + (size_t)(Cc+c)*TYn + y] = zv;
}

// -------------------- K3: logp GEMM (128x128 tile, band-pruned) ---------------
__global__ void __launch_bounds__(256, 2)
gemm_kernel(const int* __restrict__ xl, const int* __restrict__ yl)
{
    int b  = blockIdx.z;
    int x0 = blockIdx.x * 128;
    int y0 = blockIdx.y * 128;
    int xlen = xl[b], ylen = yl[b];
    if (x0 >= xlen || y0 >= ylen) return;
    // band pruning: tiles never consumed by the Viterbi DP / backtrack
    if (x0 > y0 + 127) return;                      // entirely above diagonal (x>j)
    if (x0 + 127 < y0 - (ylen - xlen)) return;      // entirely below reachable band

    __shared__ float zs[16][128];   // k x y
    __shared__ float ws[16][128];   // k x x

    int tid  = threadIdx.x;
    int lrow = tid >> 4;            // 0..15
    int lcol = (tid & 15) << 3;     // 0..120
    int ty   = tid >> 4;            // 0..15
    int tx   = tid & 15;            // 0..15

    const float* Zb = g_Z + (size_t)b*K2*TYn;
    const float* Wb = g_W + (size_t)b*K2*TXn;

    float acc[8][8] = {};

    for (int k0 = 0; k0 < K2; k0 += 16) {
        const float* zp = Zb + (size_t)(k0+lrow)*TYn + y0 + lcol;
        const float* wp = Wb + (size_t)(k0+lrow)*TXn + x0 + lcol;
        *(float4*)&zs[lrow][lcol]   = *(const float4*)zp;
        *(float4*)&zs[lrow][lcol+4] = *(const float4*)(zp+4);
        *(float4*)&ws[lrow][lcol]   = *(const float4*)wp;
        *(float4*)&ws[lrow][lcol+4] = *(const float4*)(wp+4);
        __syncthreads();
        #pragma unroll
        for (int k = 0; k < 16; k++) {
            float4 z0 = *(float4*)&zs[k][ty<<3];
            float4 z1 = *(float4*)&zs[k][(ty<<3)+4];
            float4 w0 = *(float4*)&ws[k][tx<<3];
            float4 w1 = *(float4*)&ws[k][(tx<<3)+4];
            float za[8] = {z0.x,z0.y,z0.z,z0.w,z1.x,z1.y,z1.z,z1.w};
            float wa[8] = {w0.x,w0.y,w0.z,w0.w,w1.x,w1.y,w1.z,w1.w};
            #pragma unroll
            for (int i = 0; i < 8; i++)
                #pragma unroll
                for (int j = 0; j < 8; j++)
                    acc[i][j] += za[i]*wa[j];
        }
        __syncthreads();
    }

    float ra[8];
    #pragma unroll
    for (int j = 0; j < 8; j++)
        ra[j] = g_rowA[b*TXn + x0 + (tx<<3) + j];

    #pragma unroll
    for (int i = 0; i < 8; i++) {
        int y = y0 + (ty<<3) + i;
        float* op = g_logpT + ((size_t)b*TYn + y)*TXn + x0 + (tx<<3);
        float4 o0, o1;
        float* p0 = (float*)&o0; float* p1 = (float*)&o1;
        bool yok = (y < ylen);
        #pragma unroll
        for (int j = 0; j < 4; j++) {
            int xa = x0 + (tx<<3) + j;
            int xb = xa + 4;
            p0[j] = (yok && xa < xlen) ? (acc[i][j]   + ra[j])   : 0.f;
            p1[j] = (yok && xb < xlen) ? (acc[i][j+4] + ra[j+4]) : 0.f;
        }
        *(float4*)op       = o0;
        *(float4*)(op + 4) = o1;
    }
}

// -------------------- K4: forward Viterbi (halo wavefront) ---------------------
// 512 threads, 1 main x per thread (vm) + a full 32-wide halo copy of the left
// neighbor warp's range (vh, x-32). Each warp advances 32 columns with NO
// cross-warp communication (main lane0's left = halo lane31; halo advances by
// shuffles only). Boundary exchange (publish vm / reload vh) once per 32
// columns via double-buffered smem + one __syncthreads. 64 barriers total.
__global__ void __launch_bounds__(512)
fwd_kernel(const int* __restrict__ xl, const int* __restrict__ yl)
{
    __shared__ float xch[2][16*33];   // double-buffered boundary exchange

    int b    = blockIdx.x;
    int x    = threadIdx.x;
    int w    = x >> 5, lane = x & 31;
    int xlen = xl[b], ylen = yl[b];

    unsigned force;
    {
        int rel = xlen - (w << 5);
        if (rel <= 0)      force = 0xFFFFFFFFu;
        else if (rel < 32) force = 0xFFFFFFFFu << rel;
        else               force = 0u;
    }
    int mlim_m = (w << 5) + 31;   // main x>j masking needed while j < mlim_m
    int mlim_h = (w << 5) - 1;    // halo (x-32)>j masking needed while j < mlim_h

    float vm = 0.f;
    float vh = (w == 0) ? NEGV : 0.f;

    const float* basem = g_logpT + (size_t)b*TYn*TXn + x;
    const float* baseh = basem - 32;          // only dereferenced when w > 0
    unsigned*    dbase = g_dbits + (size_t)b*TYn*16 + w;

    // parity prefetch buffers (8 columns each), reloaded in place 16 ahead
    float cm0[8], cm1[8], ch0[8], ch1[8];
    #pragma unroll
    for (int d = 0; d < 8; d++) {
        cm0[d] = (d < ylen)     ? basem[(size_t)d*TXn]       : 0.f;
        cm1[d] = (8 + d < ylen) ? basem[(size_t)(8 + d)*TXn] : 0.f;
        if (w > 0) {
            ch0[d] = (d < ylen)     ? baseh[(size_t)d*TXn]       : 0.f;
            ch1[d] = (8 + d < ylen) ? baseh[(size_t)(8 + d)*TXn] : 0.f;
        } else { ch0[d] = 0.f; ch1[d] = 0.f; }
    }

    auto colbody = [&](float (&CBm)[8], float (&CBh)[8], int j0) {
        #pragma unroll
        for (int d = 0; d < 8; d++) {
            int j = j0 + d;
            if (j < ylen) {                          // warp-uniform
                float cm = CBm[d];
                float ch = CBh[d];
                int jp = j + 16;                     // in-place reload for +2 subphases
                bool pok = (jp < ylen);
                CBm[d] = pok ? basem[(size_t)jp*TXn] : 0.f;
                if (w > 0) CBh[d] = pok ? baseh[(size_t)jp*TXn] : 0.f;

                // main update: left of lane0 = halo lane31 (current column state)
                float h31 = __shfl_sync(0xFFFFFFFFu, vh, 31);
                float lm  = __shfl_up_sync(0xFFFFFFFFu, vm, 1);
                if (lane == 0) lm = h31;

                bool  di = vm >= lm;
                float nv = fmaxf(vm, lm) + cm;
                if (j < mlim_m) { if (x > j) nv = NEGV; }

                unsigned bits = __ballot_sync(0xFFFFFFFFu, di) | force;
                if (lane == 0) dbase[(size_t)j*16] = bits;
                vm = nv;

                // halo update (warp-uniform skip for w==0)
                if (w > 0) {
                    float lh = __shfl_up_sync(0xFFFFFFFFu, vh, 1);
                    if (lane == 0) lh = NEGV;
                    float nh = fmaxf(vh, lh) + ch;
                    if (j < mlim_h) { if (x - 32 > j) nh = NEGV; }
                    vh = nh;
                }
            }
        }
    };

    int nsp = (ylen + 7) >> 3;
    for (int sp = 0; sp < nsp; sp++) {
        int j0 = sp << 3;
        if ((j0 & 31) == 0) {
            // boundary exchange: publish my main, adopt left neighbor's as halo
            int pb = (j0 >> 5) & 1;
            xch[pb][w*33 + lane] = vm;
            __syncthreads();
            vh = (w == 0) ? NEGV : xch[pb][(w-1)*33 + lane];
        }
        if (sp & 1) colbody(cm1, ch1, j0);
        else        colbody(cm0, ch0, j0);
    }
}

// -------------------- K5: backtrack + count (1 warp per batch, 32-bit words) ---
__global__ void __launch_bounds__(32)
bwd_kernel(const int* __restrict__ xl, const int* __restrict__ yl)
{
    int b = blockIdx.x, lane = threadIdx.x;
    int xlen = xl[b], ylen = yl[b];

    for (int j = ylen + lane; j < TYn; j += 32) g_xy[b*TYn + j] = 0;

    int idx = xlen - 1;
    for (int jhi = ylen - 1; jhi >= 0; jhi -= 32) {
        int steps = min(32, jhi + 1);
        int j = jhi - lane;
        int w0 = idx >> 5;                 // spans at most 2 words over 32 steps
        unsigned d0 = 0xFFFFFFFFu, d1 = 0xFFFFFFFFu;
        if (lane < steps) {
            const unsigned* p = g_dbits + ((size_t)b*TYn + j)*16;
            d0 = p[w0];
            if (w0 >= 1) d1 = p[w0-1];
        }
        int myidx = 0;
        for (int s = 0; s < steps; s++) {
            unsigned sel  = (w0 == (idx >> 5)) ? d0 : d1;
            unsigned word = __shfl_sync(0xFFFFFFFFu, sel, s);
            if (lane == s) myidx = idx;
            idx += (int)((word >> (idx & 31)) & 1u) - 1;
        }
        if (lane < steps) {
            g_xy[b*TYn + jhi - lane] = myidx;
            atomicAdd(&g_cnt[b*TXn + myidx], 1);
        }
    }
}

// -------------------- K6: y_mean / y_log_scale gathers -------------------------
__global__ void gather_kernel(const float* __restrict__ om,
                              const float* __restrict__ ols,
                              const int* __restrict__ yl,
                              float* __restrict__ out)
{
    int i = blockIdx.x * blockDim.x + threadIdx.x;
    if (i >= Bn*Cc*TYn) return;
    int b = i / (Cc*TYn);
    int r = i % (Cc*TYn);
    int c = r / TYn;
    int y = r % TYn;
    float m = 0.f, s = 0.f;
    if (y < yl[b]) {
        int x = g_xy[b*TYn + y];
        m = om [(size_t)(b*Cc + c)*TXn + x];
        s = ols[(size_t)(b*Cc + c)*TXn + x];
    }
    out[YMEAN_OFF + i] = m;
    out[YLOG_OFF  + i] = s;
}

// -------------------- K7: attn_out (zero + one-hot scatter) --------------------
__global__ void attn_kernel(const int* __restrict__ yl, float* __restrict__ out)
{
    int y = blockIdx.x, b = blockIdx.y, t = threadIdx.x;
    int xi = (y < yl[b]) ? g_xy[b*TYn + y] : -1;
    int x4 = t << 2;
    float4 r = make_float4(0.f, 0.f, 0.f, 0.f);
    if (xi >= x4 && xi < x4 + 4) ((float*)&r)[xi - x4] = 1.0f;
    *(float4*)&out[ATTN_OFF + ((size_t)b*TYn + y)*TXn + x4] = r;
}

// -------------------- K8: o_attn_dur --------------------------------------------
__global__ void dur_kernel(const int* __restrict__ xl, float* __restrict__ out)
{
    int i = blockIdx.x * blockDim.x + threadIdx.x;
    if (i >= Bn*TXn) return;
    int b = i / TXn, x = i % TXn;
    out[OADUR_OFF + i] = (x < xl[b]) ? log1pf((float)g_cnt[i]) : 0.f;
}

// -------------------- launch (single stream — forks measured harmful) -----------
extern "C" void kernel_launch(void* const* d_in, const int* in_sizes, int n_in,
                              void* d_out, int out_size)
{
    const float* om   = (const float*)d_in[0];
    const float* ols  = (const float*)d_in[1];
    const float* odur = (const float*)d_in[2];
    const float* z    = (const float*)d_in[3];
    const int*   xlen = (const int*)  d_in[4];
    const int*   ylen = (const int*)  d_in[5];
    float* out = (float*)d_out;

    prepx_kernel<<<(Bn*TXn + 255)/256, 256>>>(om, ols, odur, out);
    prepz_kernel<<<(Bn*Cc*TYn + 255)/256, 256>>>(z, ylen, out);
    gemm_kernel<<<dim3(TXn/128, TYn/128, Bn), 256>>>(xlen, ylen);
    fwd_kernel<<<Bn, 512>>>(xlen, ylen);
    bwd_kernel<<<Bn, 32>>>(xlen, ylen);
    gather_kernel<<<(Bn*Cc*TYn + 255)/256, 256>>>(om, ols, ylen, out);
    attn_kernel<<<dim3(TYn, Bn), 128>>>(ylen, out);
    dur_kernel<<<(Bn*TXn + 255)/256, 256>>>(xlen, out);
}

// round 10
// speedup vs baseline: 2.2971x; 1.9151x over previous
#include <cuda_runtime.h>
#include <cuda_bf16.h>
#include <math.h>
#include <stdint.h>

// Problem constants
#define Bn  32
#define Cc  80
#define TXn 512
#define TYn 2048
#define K2  160          // stacked K: [scale(80); mean*scale(80)]
#define NEGV (-1e9f)
#define LOG2PI 1.8378770664093453f

// Output layout (flat f32, reference return order)
#define Z_OFF        0
#define YMEAN_OFF    (Bn*Cc*TYn)
#define YLOG_OFF     (2*Bn*Cc*TYn)
#define ATTN_OFF     (3*Bn*Cc*TYn)
#define ODUR_OFF     (ATTN_OFF + Bn*TYn*TXn)
#define OADUR_OFF    (ODUR_OFF + Bn*TXn)

// -------------------- scratch (__device__ globals) --------------------------
__device__ float    g_W[Bn*K2*TXn];              // [b][k][x]
__device__ float    g_Z[Bn*K2*TYn];              // [b][k][y]
__device__ float    g_rowA[Bn*TXn];              // logp1+logp4 per (b,x)
__device__ float    g_logpT[(size_t)Bn*TYn*TXn]; // 134 MB [b][y][x]
// dir bits: per column 16 words; block blk=x>>6 owns words {2blk, 2blk+1} =
// {even-x bits, odd-x bits}; bit index = (x>>1)&31.
__device__ unsigned g_dbits[(size_t)Bn*TYn*16];
__device__ int      g_xy[Bn*TYn];                // alignment index per (b,y)
__device__ int      g_cnt[Bn*TXn];               // per-x duration counts

// -------------------- K1: per-(b,x) prep -------------------------------------
__global__ void prepx_kernel(const float* __restrict__ om,
                             const float* __restrict__ ols,
                             const float* __restrict__ odur,
                             float* __restrict__ out)
{
    int i = blockIdx.x * blockDim.x + threadIdx.x;
    if (i >= Bn*TXn) return;
    int b = i / TXn, x = i % TXn;
    const float* omb = om  + (size_t)b*Cc*TXn + x;
    const float* olb = ols + (size_t)b*Cc*TXn + x;
    float* wS = g_W + (size_t)b*K2*TXn + x;
    float sa = 0.f;
    #pragma unroll 4
    for (int c = 0; c < Cc; c++) {
        float l  = olb[(size_t)c*TXn];
        float sc = expf(-2.f*l);
        float m  = omb[(size_t)c*TXn];
        wS[(size_t)c*TXn]        = sc;
        wS[(size_t)(Cc+c)*TXn]   = m*sc;
        sa += -0.5f*LOG2PI - l - 0.5f*m*m*sc;
    }
    g_rowA[i] = sa;
    g_cnt[i]  = 0;
    out[ODUR_OFF + i] = odur[i];
}

// -------------------- K2: z masking + Z matrix --------------------------------
__global__ void prepz_kernel(const float* __restrict__ z,
                             const int* __restrict__ yl,
                             float* __restrict__ out)
{
    int i = blockIdx.x * blockDim.x + threadIdx.x;
    if (i >= Bn*Cc*TYn) return;
    int b = i / (Cc*TYn);
    int r = i % (Cc*TYn);
    int c = r / TYn;
    int y = r % TYn;
    float zv = z[i];
    if (y >= yl[b]) zv = 0.f;
    out[Z_OFF + i] = zv;
    size_t zb = (size_t)b*K2*TYn;
    g_Z[zb + (size_t)c*TYn + y]      = -0.5f*zv*zv;
    g_Z[zb + (size_t)(Cc+c)*TYn + y] = zv;
}

// -------------------- K3: logp GEMM (128x128 tile, band-pruned) ---------------
__global__ void __launch_bounds__(256, 2)
gemm_kernel(const int* __restrict__ xl, const int* __restrict__ yl)
{
    int b  = blockIdx.z;
    int x0 = blockIdx.x * 128;
    int y0 = blockIdx.y * 128;
    int xlen = xl[b], ylen = yl[b];
    if (x0 >= xlen || y0 >= ylen) return;
    // band pruning: tiles never consumed by the Viterbi DP / backtrack
    if (x0 > y0 + 127) return;                      // entirely above diagonal (x>j)
    if (x0 + 127 < y0 - (ylen - xlen)) return;      // entirely below reachable band

    __shared__ float zs[16][128];   // k x y
    __shared__ float ws[16][128];   // k x x

    int tid  = threadIdx.x;
    int lrow = tid >> 4;            // 0..15
    int lcol = (tid & 15) << 3;     // 0..120
    int ty   = tid >> 4;            // 0..15
    int tx   = tid & 15;            // 0..15

    const float* Zb = g_Z + (size_t)b*K2*TYn;
    const float* Wb = g_W + (size_t)b*K2*TXn;

    float acc[8][8] = {};

    for (int k0 = 0; k0 < K2; k0 += 16) {
        const float* zp = Zb + (size_t)(k0+lrow)*TYn + y0 + lcol;
        const float* wp = Wb + (size_t)(k0+lrow)*TXn + x0 + lcol;
        *(float4*)&zs[lrow][lcol]   = *(const float4*)zp;
        *(float4*)&zs[lrow][lcol+4] = *(const float4*)(zp+4);
        *(float4*)&ws[lrow][lcol]   = *(const float4*)wp;
        *(float4*)&ws[lrow][lcol+4] = *(const float4*)(wp+4);
        __syncthreads();
        #pragma unroll
        for (int k = 0; k < 16; k++) {
            float4 z0 = *(float4*)&zs[k][ty<<3];
            float4 z1 = *(float4*)&zs[k][(ty<<3)+4];
            float4 w0 = *(float4*)&ws[k][tx<<3];
            float4 w1 = *(float4*)&ws[k][(tx<<3)+4];
            float za[8] = {z0.x,z0.y,z0.z,z0.w,z1.x,z1.y,z1.z,z1.w};
            float wa[8] = {w0.x,w0.y,w0.z,w0.w,w1.x,w1.y,w1.z,w1.w};
            #pragma unroll
            for (int i = 0; i < 8; i++)
                #pragma unroll
                for (int j = 0; j < 8; j++)
                    acc[i][j] += za[i]*wa[j];
        }
        __syncthreads();
    }

    float ra[8];
    #pragma unroll
    for (int j = 0; j < 8; j++)
        ra[j] = g_rowA[b*TXn + x0 + (tx<<3) + j];

    #pragma unroll
    for (int i = 0; i < 8; i++) {
        int y = y0 + (ty<<3) + i;
        float* op = g_logpT + ((size_t)b*TYn + y)*TXn + x0 + (tx<<3);
        float4 o0, o1;
        float* p0 = (float*)&o0; float* p1 = (float*)&o1;
        bool yok = (y < ylen);
        #pragma unroll
        for (int j = 0; j < 4; j++) {
            int xa = x0 + (tx<<3) + j;
            int xb = xa + 4;
            p0[j] = (yok && xa < xlen) ? (acc[i][j]   + ra[j])   : 0.f;
            p1[j] = (yok && xb < xlen) ? (acc[i][j+4] + ra[j+4]) : 0.f;
        }
        *(float4*)op       = o0;
        *(float4*)(op + 4) = o1;
    }
}

// -------------------- K4: forward Viterbi (R3 structure, 2 x per thread) -------
// 256 threads; thread t owns x0=2t, x1=2t+1. Pair-internal left neighbor is
// in-register (old v0); cross-thread left via shfl of old v1; warp boundary
// (x=64w+63) via double-buffered smem + per-column __syncthreads — exactly the
// proven R3 synchronization pattern, with half the warps and half the loads.
__global__ void __launch_bounds__(256)
fwd_kernel(const int* __restrict__ xl, const int* __restrict__ yl)
{
    int b    = blockIdx.x;
    int t    = threadIdx.x;
    int w    = t >> 5, lane = t & 31;
    int xlen = xl[b], ylen = yl[b];
    int x0 = t << 1, x1 = x0 + 1;

    __shared__ float sb[2][8];        // warp-boundary v, double-buffered

    // force-stay bits: word 2w = even-x bits, word 2w+1 = odd-x bits of block
    int rel = xlen - (w << 6);
    if (rel < 0) rel = 0; if (rel > 64) rel = 64;
    int he = (rel + 1) >> 1;          // first forced even-lane index
    int ho = rel >> 1;                // first forced odd-lane index
    unsigned fe = (he >= 32) ? 0u : (0xFFFFFFFFu << he);
    unsigned fo = (ho >= 32) ? 0u : (0xFFFFFFFFu << ho);

    float v0 = 0.f, v1 = 0.f;
    if (lane == 31) { sb[0][w] = 0.f; sb[1][w] = 0.f; }

    const float2* base2 = (const float2*)(g_logpT + (size_t)b*TYn*TXn) + t;
    const int str2 = TXn / 2;
    unsigned* dbase = g_dbits + (size_t)b*TYn*16 + (w << 1);

    const int PF = 8;
    float2 c[PF];
    #pragma unroll
    for (int d = 0; d < PF; d++)
        c[d] = (d < ylen) ? base2[(size_t)d*str2] : make_float2(0.f, 0.f);
    __syncthreads();

    for (int j0 = 0; j0 < ylen; j0 += PF) {
        float2 cn[PF];
        #pragma unroll
        for (int d = 0; d < PF; d++) {
            int j = j0 + d;
            if (j < ylen) {                      // uniform per block
                int jp = j + PF;
                cn[d] = (jp < ylen) ? base2[(size_t)jp*str2] : make_float2(0.f, 0.f);

                float left = __shfl_up_sync(0xFFFFFFFFu, v1, 1);
                if (lane == 0) left = (w == 0) ? NEGV : sb[j & 1][w - 1];

                bool  d0 = v0 >= left;
                bool  d1 = v1 >= v0;
                float nv0 = fmaxf(v0, left) + c[d].x;
                float nv1 = fmaxf(v1, v0)   + c[d].y;
                if (x0 > j) nv0 = NEGV;
                if (x1 > j) nv1 = NEGV;

                unsigned be = __ballot_sync(0xFFFFFFFFu, d0) | fe;
                unsigned bo = __ballot_sync(0xFFFFFFFFu, d1) | fo;
                if (lane == 0)
                    *(uint2*)&dbase[(size_t)j*16] = make_uint2(be, bo);

                v0 = nv0; v1 = nv1;
                if (lane == 31) sb[(j + 1) & 1][w] = v1;
                __syncthreads();
            }
        }
        #pragma unroll
        for (int d = 0; d < PF; d++) c[d] = cn[d];
    }
}

// -------------------- K5: backtrack + count (1 warp per batch) -----------------
// dir bit of x at column j: word 2*(x>>6) + (x&1), bit (x>>1)&31.
// Over 32 steps idx spans <=2 blocks of 64 -> preload 4 words per lane.
__global__ void __launch_bounds__(32)
bwd_kernel(const int* __restrict__ xl, const int* __restrict__ yl)
{
    int b = blockIdx.x, lane = threadIdx.x;
    int xlen = xl[b], ylen = yl[b];

    for (int j = ylen + lane; j < TYn; j += 32) g_xy[b*TYn + j] = 0;

    int idx = xlen - 1;
    for (int jhi = ylen - 1; jhi >= 0; jhi -= 32) {
        int steps = min(32, jhi + 1);
        int j = jhi - lane;
        int blk0 = idx >> 6;
        unsigned e0 = 0xFFFFFFFFu, o0 = 0xFFFFFFFFu;
        unsigned e1 = 0xFFFFFFFFu, o1 = 0xFFFFFFFFu;
        if (lane < steps) {
            const unsigned* p = g_dbits + ((size_t)b*TYn + j)*16;
            e0 = p[(blk0 << 1)];
            o0 = p[(blk0 << 1) + 1];
            if (blk0 >= 1) {
                e1 = p[(blk0 << 1) - 2];
                o1 = p[(blk0 << 1) - 1];
            }
        }
        int myidx = 0;
        for (int s = 0; s < steps; s++) {
            bool near = ((idx >> 6) == blk0);
            bool odd  = (idx & 1);
            unsigned sel = near ? (odd ? o0 : e0) : (odd ? o1 : e1);
            unsigned word = __shfl_sync(0xFFFFFFFFu, sel, s);
            if (lane == s) myidx = idx;
            idx += (int)((word >> ((idx >> 1) & 31)) & 1u) - 1;
        }
        if (lane < steps) {
            g_xy[b*TYn + jhi - lane] = myidx;
            atomicAdd(&g_cnt[b*TXn + myidx], 1);
        }
    }
}

// -------------------- K6: y_mean / y_log_scale gathers -------------------------
__global__ void gather_kernel(const float* __restrict__ om,
                              const float* __restrict__ ols,
                              const int* __restrict__ yl,
                              float* __restrict__ out)
{
    int i = blockIdx.x * blockDim.x + threadIdx.x;
    if (i >= Bn*Cc*TYn) return;
    int b = i / (Cc*TYn);
    int r = i % (Cc*TYn);
    int c = r / TYn;
    int y = r % TYn;
    float m = 0.f, s = 0.f;
    if (y < yl[b]) {
        int x = g_xy[b*TYn + y];
        m = om [(size_t)(b*Cc + c)*TXn + x];
        s = ols[(size_t)(b*Cc + c)*TXn + x];
    }
    out[YMEAN_OFF + i] = m;
    out[YLOG_OFF  + i] = s;
}

// -------------------- K7: attn_out (zero + one-hot scatter) --------------------
__global__ void attn_kernel(const int* __restrict__ yl, float* __restrict__ out)
{
    int y = blockIdx.x, b = blockIdx.y, t = threadIdx.x;
    int xi = (y < yl[b]) ? g_xy[b*TYn + y] : -1;
    int x4 = t << 2;
    float4 r = make_float4(0.f, 0.f, 0.f, 0.f);
    if (xi >= x4 && xi < x4 + 4) ((float*)&r)[xi - x4] = 1.0f;
    *(float4*)&out[ATTN_OFF + ((size_t)b*TYn + y)*TXn + x4] = r;
}

// -------------------- K8: o_attn_dur --------------------------------------------
__global__ void dur_kernel(const int* __restrict__ xl, float* __restrict__ out)
{
    int i = blockIdx.x * blockDim.x + threadIdx.x;
    if (i >= Bn*TXn) return;
    int b = i / TXn, x = i % TXn;
    out[OADUR_OFF + i] = (x < xl[b]) ? log1pf((float)g_cnt[i]) : 0.f;
}

// -------------------- launch (single stream) -------------------------------------
extern "C" void kernel_launch(void* const* d_in, const int* in_sizes, int n_in,
                              void* d_out, int out_size)
{
    const float* om   = (const float*)d_in[0];
    const float* ols  = (const float*)d_in[1];
    const float* odur = (const float*)d_in[2];
    const float* z    = (const float*)d_in[3];
    const int*   xlen = (const int*)  d_in[4];
    const int*   ylen = (const int*)  d_in[5];
    float* out = (float*)d_out;

    prepx_kernel<<<(Bn*TXn + 255)/256, 256>>>(om, ols, odur, out);
    prepz_kernel<<<(Bn*Cc*TYn + 255)/256, 256>>>(z, ylen, out);
    gemm_kernel<<<dim3(TXn/128, TYn/128, Bn), 256>>>(xlen, ylen);
    fwd_kernel<<<Bn, 256>>>(xlen, ylen);
    bwd_kernel<<<Bn, 32>>>(xlen, ylen);
    gather_kernel<<<(Bn*Cc*TYn + 255)/256, 256>>>(om, ols, ylen, out);
    attn_kernel<<<dim3(TYn, Bn), 128>>>(ylen, out);
    dur_kernel<<<(Bn*TXn + 255)/256, 256>>>(xlen, out);
}